// round 5
// baseline (speedup 1.0000x reference)
#include <cuda_runtime.h>
#include <math.h>

#define NN   2048
#define BB   8
#define HH   4
#define DD   64
#define SEG1 (BB*HH)     // 32 segments in layer 1
#define CH   16          // scan chunks per segment
#define CL   (NN/CH)     // 128 elements per chunk
#define ALPHA_ 0.2f

// ---------------- scratch (static __device__, no allocation) ----------------
__device__ float g_Hbuf [SEG1 * NN * DD];            // layer-1 per-head h (pre-attention)
__device__ float g_H2   [BB   * NN * DD];            // layer-2 h
__device__ float g_s1   [SEG1 * NN];
__device__ float g_s2   [SEG1 * NN];
__device__ float g_sorted[SEG1 * NN];
__device__ int   g_perm [SEG1 * NN];
__device__ float g_wpre [SEG1 * NN];                 // e^{alpha*(s2-s2max)} sorted order
__device__ float g_wsuf [SEG1 * NN];                 // e^{(s2-s2max)} sorted order
__device__ float g_smax [SEG1];
__device__ float g_CT   [SEG1 * CH * 128];           // chunk totals / offsets
__device__ float g_A1   [SEG1 * (NN+1)];             // scalar prefix of wpre
__device__ float g_B1   [SEG1 * (NN+1)];             // scalar SUFFIX of wsuf
__device__ float g_Ah   [SEG1 * (NN+1) * DD];        // vector prefix of wpre*h
__device__ float g_Bh   [SEG1 * (NN+1) * DD];        // vector SUFFIX of wsuf*h
__device__ float g_XC   [BB * NN * HH * DD];         // concat of elu(head outputs)

// ---------------- GEMM: Hout = X @ W[head], plus s1 = h@a[:64], s2 = h@a[64:] ----------------
// Block: 256 threads computes a 64-row x 64-col tile. Thread = 4 rows x 4 cols.
__global__ __launch_bounds__(256)
void gemm_kernel(const float* __restrict__ Xin,
                 const float* __restrict__ Wmat,
                 const float* __restrict__ avec,
                 int K, int Hcount, int xsel, int layer) {
    __shared__ float XsT[64][68];   // [k][r], padded
    __shared__ float Ws [64][64];   // [k][d]
    const float* X    = xsel ? g_XC : Xin;
    float*       Hout = (layer == 1) ? g_Hbuf : g_H2;

    const int tid  = threadIdx.x;
    const int head = blockIdx.y;
    const int R0   = blockIdx.x * 64;
    const int rq   = tid >> 4;     // 0..15 -> rows rq*4..rq*4+3
    const int cq   = tid & 15;     // 0..15 -> dims cq*4..cq*4+3

    float acc[4][4];
#pragma unroll
    for (int i = 0; i < 4; i++)
#pragma unroll
        for (int j = 0; j < 4; j++) acc[i][j] = 0.f;

    for (int kp = 0; kp < K; kp += 64) {
        __syncthreads();
#pragma unroll
        for (int i = 0; i < 16; i++) {
            int idx = tid + i * 256;
            int r = idx >> 6, k = idx & 63;
            XsT[k][r] = X[(size_t)(R0 + r) * K + kp + k];
        }
#pragma unroll
        for (int i = 0; i < 16; i++) {
            int idx = tid + i * 256;
            int k = idx >> 6, d = idx & 63;
            Ws[k][d] = Wmat[((size_t)head * K + kp + k) * 64 + d];
        }
        __syncthreads();
#pragma unroll 16
        for (int k = 0; k < 64; k++) {
            float4 xv = *(const float4*)&XsT[k][rq * 4];
            float4 wv = *(const float4*)&Ws [k][cq * 4];
            acc[0][0] += xv.x*wv.x; acc[0][1] += xv.x*wv.y; acc[0][2] += xv.x*wv.z; acc[0][3] += xv.x*wv.w;
            acc[1][0] += xv.y*wv.x; acc[1][1] += xv.y*wv.y; acc[1][2] += xv.y*wv.z; acc[1][3] += xv.y*wv.w;
            acc[2][0] += xv.z*wv.x; acc[2][1] += xv.z*wv.y; acc[2][2] += xv.z*wv.z; acc[2][3] += xv.z*wv.w;
            acc[3][0] += xv.w*wv.x; acc[3][1] += xv.w*wv.y; acc[3][2] += xv.w*wv.z; acc[3][3] += xv.w*wv.w;
        }
    }

    float a1v[4], a2v[4];
#pragma unroll
    for (int j = 0; j < 4; j++) {
        a1v[j] = __ldg(&avec[head * 128 + cq * 4 + j]);
        a2v[j] = __ldg(&avec[head * 128 + 64 + cq * 4 + j]);
    }

#pragma unroll
    for (int i = 0; i < 4; i++) {
        int R = R0 + rq * 4 + i;
        int g = R >> 11;            // N = 2048
        int n = R & (NN - 1);
        int seg = g * Hcount + head;
        size_t base = ((size_t)seg * NN + n) * 64 + cq * 4;
        float4 v; v.x = acc[i][0]; v.y = acc[i][1]; v.z = acc[i][2]; v.w = acc[i][3];
        *(float4*)&Hout[base] = v;

        float p1 = acc[i][0]*a1v[0] + acc[i][1]*a1v[1] + acc[i][2]*a1v[2] + acc[i][3]*a1v[3];
        float p2 = acc[i][0]*a2v[0] + acc[i][1]*a2v[1] + acc[i][2]*a2v[2] + acc[i][3]*a2v[3];
#pragma unroll
        for (int off = 8; off; off >>= 1) {
            p1 += __shfl_down_sync(0xffffffffu, p1, off, 16);
            p2 += __shfl_down_sync(0xffffffffu, p2, off, 16);
        }
        if (cq == 0) {
            g_s1[seg * NN + n] = p1;
            g_s2[seg * NN + n] = p2;
        }
    }
}

// ---------------- bitonic sort of s2 (ascending) per segment, + exp weights ----------------
__global__ __launch_bounds__(256)
void sort_kernel() {
    __shared__ float key[NN];
    __shared__ int   idx[NN];
    const int seg = blockIdx.x, tid = threadIdx.x;

    for (int i = tid; i < NN; i += 256) { key[i] = g_s2[seg * NN + i]; idx[i] = i; }

    for (int k = 2; k <= NN; k <<= 1) {
        for (int j = k >> 1; j > 0; j >>= 1) {
            __syncthreads();
            for (int t = tid; t < NN; t += 256) {
                int x = t ^ j;
                if (x > t) {
                    bool up = ((t & k) == 0);
                    float ka = key[t], kb = key[x];
                    if ((ka > kb) == up) {
                        key[t] = kb; key[x] = ka;
                        int tmp = idx[t]; idx[t] = idx[x]; idx[x] = tmp;
                    }
                }
            }
        }
    }
    __syncthreads();

    float smaxv = key[NN - 1];
    for (int i = tid; i < NN; i += 256) {
        float kk = key[i];
        g_sorted[seg * NN + i] = kk;
        g_perm  [seg * NN + i] = idx[i];
        g_wsuf  [seg * NN + i] = expf(kk - smaxv);
        g_wpre  [seg * NN + i] = expf(ALPHA_ * (kk - smaxv));
    }
    if (tid == 0) g_smax[seg] = smaxv;
}

// ---------------- pass 3a: per-chunk vector sums ----------------
// threads 0..63 -> wpre*h (A half), 64..127 -> wsuf*h (B half)
__global__ __launch_bounds__(128)
void pass3a_kernel(int layer) {
    const int seg = blockIdx.x, c = blockIdx.y, tid = threadIdx.x;
    const float* Hmat = (layer == 1) ? g_Hbuf : g_H2;
    const int d = tid & 63;
    const float* w = (tid < 64) ? g_wpre : g_wsuf;
    const int q0 = c * CL;
    float acc = 0.f;
#pragma unroll 4
    for (int q = q0; q < q0 + CL; q++) {
        int   ix = __ldg(&g_perm[seg * NN + q]);
        float wv = __ldg(&w[seg * NN + q]);
        acc += wv * __ldg(&Hmat[((size_t)seg * NN + ix) * 64 + d]);
    }
    g_CT[(seg * CH + c) * 128 + tid] = acc;
}

// ---------------- pass 3b: scan chunk totals + full scalar scans ----------------
__global__ __launch_bounds__(256)
void pass3b_kernel() {
    const int seg = blockIdx.x, tid = threadIdx.x;

    // (a) vector chunk offsets: A forward-exclusive, B suffix-exclusive (reverse)
    if (tid < 128) {
        if (tid < 64) {
            float run = 0.f;
            for (int c = 0; c < CH; c++) {
                int o = (seg * CH + c) * 128 + tid;
                float v = g_CT[o]; g_CT[o] = run; run += v;
            }
            g_Ah[((size_t)seg * (NN + 1) + NN) * 64 + tid] = run;   // total at p=N
        } else {
            float run = 0.f;
            for (int c = CH - 1; c >= 0; c--) {
                int o = (seg * CH + c) * 128 + tid;
                float v = g_CT[o]; g_CT[o] = run; run += v;
            }
            g_Bh[((size_t)seg * (NN + 1) + NN) * 64 + (tid - 64)] = 0.f;  // suffix at p=N
        }
    }

    // (b) scalar scans: A1 = exclusive prefix of wpre, B1 = inclusive suffix of wsuf
    __shared__ float sA[256], sB[256];
    const int qb = tid * 8;
    float la[8], lb[8];
    float sa = 0.f;
#pragma unroll
    for (int i = 0; i < 8; i++) { la[i] = sa; sa += __ldg(&g_wpre[seg * NN + qb + i]); }
    float sb = 0.f;
#pragma unroll
    for (int i = 7; i >= 0; i--) { sb += __ldg(&g_wsuf[seg * NN + qb + i]); lb[i] = sb; }
    sA[tid] = sa; sB[tid] = sb;
    __syncthreads();
    if (tid == 0) {
        float r = 0.f;
        for (int t = 0; t < 256; t++) { float x = sA[t]; sA[t] = r; r += x; }
        g_A1[seg * (NN + 1) + NN] = r;
        r = 0.f;
        for (int t = 255; t >= 0; t--) { float x = sB[t]; sB[t] = r; r += x; }
        g_B1[seg * (NN + 1) + NN] = 0.f;
    }
    __syncthreads();
    float oa = sA[tid], ob = sB[tid];
#pragma unroll
    for (int i = 0; i < 8; i++) {
        g_A1[seg * (NN + 1) + qb + i] = oa + la[i];
        g_B1[seg * (NN + 1) + qb + i] = ob + lb[i];
    }
}

// ---------------- pass 3c: write full vector prefix/suffix arrays ----------------
__global__ __launch_bounds__(128)
void pass3c_kernel(int layer) {
    const int seg = blockIdx.x, c = blockIdx.y, tid = threadIdx.x;
    const float* Hmat = (layer == 1) ? g_Hbuf : g_H2;
    const int d = tid & 63;
    const int q0 = c * CL;
    float run = g_CT[(seg * CH + c) * 128 + tid];

    if (tid < 64) {  // A half: forward, write-before-add (exclusive prefix)
        for (int q = q0; q < q0 + CL; q++) {
            g_Ah[((size_t)seg * (NN + 1) + q) * 64 + d] = run;
            int   ix = __ldg(&g_perm[seg * NN + q]);
            float wv = __ldg(&g_wpre[seg * NN + q]);
            run += wv * __ldg(&Hmat[((size_t)seg * NN + ix) * 64 + d]);
        }
    } else {         // B half: reverse, add-then-write (inclusive suffix)
        for (int q = q0 + CL - 1; q >= q0; q--) {
            int   ix = __ldg(&g_perm[seg * NN + q]);
            float wv = __ldg(&g_wsuf[seg * NN + q]);
            run += wv * __ldg(&Hmat[((size_t)seg * NN + ix) * 64 + d]);
            g_Bh[((size_t)seg * (NN + 1) + q) * 64 + d] = run;
        }
    }
}

// shared combine math: returns attention output element (pre-activation)
__device__ __forceinline__ float combine_elem(int seg, int n, int d) {
    float s1v  = g_s1[seg * NN + n];
    float smax = g_smax[seg];
    float u = s1v + smax;
    float m = (u >= 0.f) ? u : ALPHA_ * u;
    float f1 = expf(u - m);
    float f2 = expf(ALPHA_ * u - m);
    float tau = -s1v;
    const float* srt = g_sorted + seg * NN;
    int lo = 0, hi = NN;
    while (lo < hi) {
        int mid = (lo + hi) >> 1;
        if (__ldg(srt + mid) < tau) lo = mid + 1; else hi = mid;
    }
    int p = lo;
    size_t rb = ((size_t)seg * (NN + 1) + p) * 64 + d;
    float Ahv = g_Ah[rb];
    float Bhv = g_Bh[rb];
    float A1v = g_A1[seg * (NN + 1) + p];
    float B1v = g_B1[seg * (NN + 1) + p];
    float num = f1 * Bhv + f2 * Ahv;
    float den = f1 * B1v + f2 * A1v;
    return num / den;
}

// ---------------- layer-1 combine: elu -> XC ----------------
__global__ __launch_bounds__(256)
void combine1_kernel() {
    const int seg = blockIdx.y, tid = threadIdx.x;
    const int n = blockIdx.x * 4 + (tid >> 6);
    const int d = tid & 63;
    float o = combine_elem(seg, n, d);
    o = (o > 0.f) ? o : expm1f(o);
    int g = seg >> 2, h = seg & 3;
    g_XC[((size_t)g * NN + n) * (HH * DD) + h * DD + d] = o;
}

// ---------------- layer-2 combine: elu -> log_softmax -> out ----------------
__global__ __launch_bounds__(256)
void combine2_kernel(float* __restrict__ out) {
    const int seg = blockIdx.y, tid = threadIdx.x;   // seg = graph g
    const int n = blockIdx.x * 4 + (tid >> 6);
    const int d = tid & 63;
    float o = combine_elem(seg, n, d);
    o = (o > 0.f) ? o : expm1f(o);

    // log_softmax over the 64 dims (2 warps per row)
    const int rl = tid >> 6;            // row within block
    const int lane = tid & 31;
    const int wh = (tid >> 5) & 1;      // warp half within row
    __shared__ float smx[4][2], ssm[4][2];

    float m = o;
#pragma unroll
    for (int off = 16; off; off >>= 1) m = fmaxf(m, __shfl_xor_sync(0xffffffffu, m, off));
    if (lane == 0) smx[rl][wh] = m;
    __syncthreads();
    float mx = fmaxf(smx[rl][0], smx[rl][1]);
    float e = expf(o - mx);
    float s = e;
#pragma unroll
    for (int off = 16; off; off >>= 1) s += __shfl_xor_sync(0xffffffffu, s, off);
    if (lane == 0) ssm[rl][wh] = s;
    __syncthreads();
    float tot = ssm[rl][0] + ssm[rl][1];

    out[((size_t)seg * NN + n) * DD + d] = o - mx - logf(tot);
}

// ---------------- launch ----------------
extern "C" void kernel_launch(void* const* d_in, const int* in_sizes, int n_in,
                              void* d_out, int out_size) {
    const float* h_states = (const float*)d_in[0];
    const float* W_heads  = (const float*)d_in[1];
    const float* a_heads  = (const float*)d_in[2];
    const float* W_out    = (const float*)d_in[3];
    const float* a_out    = (const float*)d_in[4];
    float* out = (float*)d_out;

    // ---- layer 1 (per graph, per head) ----
    gemm_kernel<<<dim3(BB * NN / 64, HH), 256>>>(h_states, W_heads, a_heads, 64, HH, 0, 1);
    sort_kernel<<<SEG1, 256>>>();
    pass3a_kernel<<<dim3(SEG1, CH), 128>>>(1);
    pass3b_kernel<<<SEG1, 256>>>();
    pass3c_kernel<<<dim3(SEG1, CH), 128>>>(1);
    combine1_kernel<<<dim3(NN / 4, SEG1), 256>>>();

    // ---- layer 2 (per graph) ----
    gemm_kernel<<<dim3(BB * NN / 64, 1), 256>>>(nullptr, W_out, a_out, 256, 1, 1, 2);
    sort_kernel<<<BB, 256>>>();
    pass3a_kernel<<<dim3(BB, CH), 128>>>(2);
    pass3b_kernel<<<BB, 256>>>();
    pass3c_kernel<<<dim3(BB, CH), 128>>>(2);
    combine2_kernel<<<dim3(NN / 4, BB), 256>>>(out);
}

// round 6
// speedup vs baseline: 1.5286x; 1.5286x over previous
#include <cuda_runtime.h>
#include <math.h>

#define NN   2048
#define BB   8
#define HH   4
#define DD   64
#define SEG1 (BB*HH)     // 32 segments in layer 1
#define CH   32          // scan chunks per segment
#define CL   (NN/CH)     // 64 elements per chunk
#define ALPHA_ 0.2f

// ---------------- scratch (static __device__, no allocation) ----------------
__device__ float g_Hbuf [SEG1 * NN * DD];            // layer-1 per-head h (pre-attention)
__device__ float g_H2   [BB   * NN * DD];            // layer-2 h
__device__ float g_s1   [SEG1 * NN];
__device__ float g_s2   [SEG1 * NN];
__device__ float g_sorted[SEG1 * NN];
__device__ int   g_perm [SEG1 * NN];
__device__ float g_wpre [SEG1 * NN];                 // e^{alpha*(s2-s2max)} sorted order
__device__ float g_wsuf [SEG1 * NN];                 // e^{(s2-s2max)} sorted order
__device__ float g_smax [SEG1];
__device__ float g_CT   [SEG1 * CH * 128];           // chunk totals / offsets
__device__ float g_A1   [SEG1 * (NN+1)];             // scalar prefix of wpre
__device__ float g_B1   [SEG1 * (NN+1)];             // scalar SUFFIX of wsuf
__device__ float g_Ah   [SEG1 * (NN+1) * DD];        // vector prefix of wpre*h
__device__ float g_Bh   [SEG1 * (NN+1) * DD];        // vector SUFFIX of wsuf*h
__device__ float g_XC   [BB * NN * HH * DD];         // concat of elu(head outputs)

// ---------------- GEMM: Hout = X @ W[head], plus s1 = h@a[:64], s2 = h@a[64:] ----------------
__global__ __launch_bounds__(256)
void gemm_kernel(const float* __restrict__ Xin,
                 const float* __restrict__ Wmat,
                 const float* __restrict__ avec,
                 int K, int Hcount, int xsel, int layer) {
    __shared__ float XsT[64][68];   // [k][r], padded
    __shared__ float Ws [64][64];   // [k][d]
    const float* X    = xsel ? g_XC : Xin;
    float*       Hout = (layer == 1) ? g_Hbuf : g_H2;

    const int tid  = threadIdx.x;
    const int head = blockIdx.y;
    const int R0   = blockIdx.x * 64;
    const int rq   = tid >> 4;
    const int cq   = tid & 15;

    float acc[4][4];
#pragma unroll
    for (int i = 0; i < 4; i++)
#pragma unroll
        for (int j = 0; j < 4; j++) acc[i][j] = 0.f;

    for (int kp = 0; kp < K; kp += 64) {
        __syncthreads();
#pragma unroll
        for (int i = 0; i < 16; i++) {
            int idx = tid + i * 256;
            int r = idx >> 6, k = idx & 63;
            XsT[k][r] = X[(size_t)(R0 + r) * K + kp + k];
        }
#pragma unroll
        for (int i = 0; i < 16; i++) {
            int idx = tid + i * 256;
            int k = idx >> 6, d = idx & 63;
            Ws[k][d] = Wmat[((size_t)head * K + kp + k) * 64 + d];
        }
        __syncthreads();
#pragma unroll 16
        for (int k = 0; k < 64; k++) {
            float4 xv = *(const float4*)&XsT[k][rq * 4];
            float4 wv = *(const float4*)&Ws [k][cq * 4];
            acc[0][0] += xv.x*wv.x; acc[0][1] += xv.x*wv.y; acc[0][2] += xv.x*wv.z; acc[0][3] += xv.x*wv.w;
            acc[1][0] += xv.y*wv.x; acc[1][1] += xv.y*wv.y; acc[1][2] += xv.y*wv.z; acc[1][3] += xv.y*wv.w;
            acc[2][0] += xv.z*wv.x; acc[2][1] += xv.z*wv.y; acc[2][2] += xv.z*wv.z; acc[2][3] += xv.z*wv.w;
            acc[3][0] += xv.w*wv.x; acc[3][1] += xv.w*wv.y; acc[3][2] += xv.w*wv.z; acc[3][3] += xv.w*wv.w;
        }
    }

    float a1v[4], a2v[4];
#pragma unroll
    for (int j = 0; j < 4; j++) {
        a1v[j] = __ldg(&avec[head * 128 + cq * 4 + j]);
        a2v[j] = __ldg(&avec[head * 128 + 64 + cq * 4 + j]);
    }

#pragma unroll
    for (int i = 0; i < 4; i++) {
        int R = R0 + rq * 4 + i;
        int g = R >> 11;
        int n = R & (NN - 1);
        int seg = g * Hcount + head;
        size_t base = ((size_t)seg * NN + n) * 64 + cq * 4;
        float4 v; v.x = acc[i][0]; v.y = acc[i][1]; v.z = acc[i][2]; v.w = acc[i][3];
        *(float4*)&Hout[base] = v;

        float p1 = acc[i][0]*a1v[0] + acc[i][1]*a1v[1] + acc[i][2]*a1v[2] + acc[i][3]*a1v[3];
        float p2 = acc[i][0]*a2v[0] + acc[i][1]*a2v[1] + acc[i][2]*a2v[2] + acc[i][3]*a2v[3];
#pragma unroll
        for (int off = 8; off; off >>= 1) {
            p1 += __shfl_down_sync(0xffffffffu, p1, off, 16);
            p2 += __shfl_down_sync(0xffffffffu, p2, off, 16);
        }
        if (cq == 0) {
            g_s1[seg * NN + n] = p1;
            g_s2[seg * NN + n] = p2;
        }
    }
}

// ---------------- bitonic sort: 1024 threads, exactly one comparator each ----------------
__global__ __launch_bounds__(1024)
void sort_kernel() {
    __shared__ float key[NN];
    __shared__ int   idx[NN];
    const int seg = blockIdx.x, tid = threadIdx.x;

    key[tid]        = g_s2[seg * NN + tid];        idx[tid]        = tid;
    key[tid + 1024] = g_s2[seg * NN + tid + 1024]; idx[tid + 1024] = tid + 1024;

    for (int k = 2; k <= NN; k <<= 1) {
        for (int j = k >> 1; j > 0; j >>= 1) {
            __syncthreads();
            int i = ((tid & ~(j - 1)) << 1) | (tid & (j - 1));
            int p = i | j;
            bool up = ((i & k) == 0);
            float ka = key[i], kb = key[p];
            if ((ka > kb) == up) {
                key[i] = kb; key[p] = ka;
                int t = idx[i]; idx[i] = idx[p]; idx[p] = t;
            }
        }
    }
    __syncthreads();

    float smaxv = key[NN - 1];
#pragma unroll
    for (int u = 0; u < 2; u++) {
        int i = tid + u * 1024;
        float kk = key[i];
        g_sorted[seg * NN + i] = kk;
        g_perm  [seg * NN + i] = idx[i];
        g_wsuf  [seg * NN + i] = expf(kk - smaxv);
        g_wpre  [seg * NN + i] = expf(ALPHA_ * (kk - smaxv));
    }
    if (tid == 0) g_smax[seg] = smaxv;
}

// ---------------- pass 3a: per-chunk vector sums (staged indices, high MLP) ----------------
__global__ __launch_bounds__(128)
void pass3a_kernel(int layer) {
    const int seg = blockIdx.x, c = blockIdx.y, tid = threadIdx.x;
    const float* Hmat = (layer == 1) ? g_Hbuf : g_H2;
    const int d = tid & 63;
    const int q0 = c * CL;

    __shared__ int   sp[CL];
    __shared__ float swA[CL], swB[CL];
    if (tid < CL) {
        sp[tid] = g_perm[seg * NN + q0 + tid];
    } else {
        int q = tid - 64;                         // CL == 64
        swA[q] = g_wpre[seg * NN + q0 + q];
        swB[q] = g_wsuf[seg * NN + q0 + q];
    }
    __syncthreads();

    const float* sw = (tid < 64) ? swA : swB;
    const size_t segNN = (size_t)seg * NN;
    float acc = 0.f;
#pragma unroll 8
    for (int q = 0; q < CL; q++) {
        acc += sw[q] * __ldg(&Hmat[(segNN + sp[q]) * 64 + d]);
    }
    g_CT[(seg * CH + c) * 128 + tid] = acc;
}

// ---------------- pass 3b: parallel scans (register chunk scan + warp shuffle scans) ----------------
__global__ __launch_bounds__(256)
void pass3b_kernel() {
    const int seg = blockIdx.x, tid = threadIdx.x;
    const int lane = tid & 31, wid = tid >> 5;
    __shared__ float wsumA[8], wsumB[8], woffA[8], woffB[8];

    // (a) vector chunk offsets: load all CH values, scan in registers
    if (tid < 128) {
        float v[CH];
#pragma unroll
        for (int c = 0; c < CH; c++) v[c] = g_CT[(seg * CH + c) * 128 + tid];
        if (tid < 64) {
            float run = 0.f;
#pragma unroll
            for (int c = 0; c < CH; c++) { float t = v[c]; g_CT[(seg * CH + c) * 128 + tid] = run; run += t; }
            g_Ah[((size_t)seg * (NN + 1) + NN) * 64 + tid] = run;
        } else {
            float run = 0.f;
#pragma unroll
            for (int c = CH - 1; c >= 0; c--) { float t = v[c]; g_CT[(seg * CH + c) * 128 + tid] = run; run += t; }
            g_Bh[((size_t)seg * (NN + 1) + NN) * 64 + (tid - 64)] = 0.f;
        }
    }

    // (b) scalar scans: A1 = exclusive prefix of wpre, B1 = inclusive suffix of wsuf
    const int qb = tid * 8;
    float wa[8], wb[8];
    {
        float4 t0 = *(const float4*)&g_wpre[seg * NN + qb];
        float4 t1 = *(const float4*)&g_wpre[seg * NN + qb + 4];
        wa[0]=t0.x; wa[1]=t0.y; wa[2]=t0.z; wa[3]=t0.w;
        wa[4]=t1.x; wa[5]=t1.y; wa[6]=t1.z; wa[7]=t1.w;
        float4 u0 = *(const float4*)&g_wsuf[seg * NN + qb];
        float4 u1 = *(const float4*)&g_wsuf[seg * NN + qb + 4];
        wb[0]=u0.x; wb[1]=u0.y; wb[2]=u0.z; wb[3]=u0.w;
        wb[4]=u1.x; wb[5]=u1.y; wb[6]=u1.z; wb[7]=u1.w;
    }
    float la[8], lb[8];
    float sa = 0.f;
#pragma unroll
    for (int i = 0; i < 8; i++) { la[i] = sa; sa += wa[i]; }
    float sb = 0.f;
#pragma unroll
    for (int i = 7; i >= 0; i--) { sb += wb[i]; lb[i] = sb; }

    // warp inclusive prefix scan of sa
    float xa = sa;
#pragma unroll
    for (int off = 1; off < 32; off <<= 1) {
        float y = __shfl_up_sync(0xffffffffu, xa, off);
        if (lane >= off) xa += y;
    }
    float exA = xa - sa;
    // warp inclusive suffix scan of sb
    float xb = sb;
#pragma unroll
    for (int off = 1; off < 32; off <<= 1) {
        float y = __shfl_down_sync(0xffffffffu, xb, off);
        if (lane < 32 - off) xb += y;
    }
    float exB = xb - sb;

    if (lane == 31) wsumA[wid] = xa;
    if (lane == 0)  wsumB[wid] = xb;
    __syncthreads();
    if (tid == 0) {
        float r = 0.f;
        for (int w = 0; w < 8; w++) { float t = wsumA[w]; woffA[w] = r; r += t; }
        g_A1[seg * (NN + 1) + NN] = r;
        r = 0.f;
        for (int w = 7; w >= 0; w--) { float t = wsumB[w]; woffB[w] = r; r += t; }
        g_B1[seg * (NN + 1) + NN] = 0.f;
    }
    __syncthreads();
    float oa = woffA[wid] + exA, ob = woffB[wid] + exB;
#pragma unroll
    for (int i = 0; i < 8; i++) {
        g_A1[seg * (NN + 1) + qb + i] = oa + la[i];
        g_B1[seg * (NN + 1) + qb + i] = ob + lb[i];
    }
}

// ---------------- pass 3c: full vector prefix/suffix arrays (depth-4 prefetch pipeline) ----------------
__global__ __launch_bounds__(128)
void pass3c_kernel(int layer) {
    const int seg = blockIdx.x, c = blockIdx.y, tid = threadIdx.x;
    const float* __restrict__ Hmat = (layer == 1) ? g_Hbuf : g_H2;
    const int d = tid & 63;
    const int q0 = c * CL;

    __shared__ int   sp[CL];
    __shared__ float swA[CL], swB[CL];
    if (tid < CL) {
        sp[tid] = g_perm[seg * NN + q0 + tid];
    } else {
        int q = tid - 64;
        swA[q] = g_wpre[seg * NN + q0 + q];
        swB[q] = g_wsuf[seg * NN + q0 + q];
    }
    __syncthreads();

    const size_t segNN = (size_t)seg * NN;
    const size_t rowbase = ((size_t)seg * (NN + 1) + q0) * 64 + d;
    float run = g_CT[(seg * CH + c) * 128 + tid];

    if (tid < 64) {  // forward, exclusive prefix of wpre*h
        float hbuf[4];
#pragma unroll
        for (int i = 0; i < 4; i++) hbuf[i] = __ldg(&Hmat[(segNN + sp[i]) * 64 + d]);
#pragma unroll 4
        for (int t = 0; t < CL; t++) {
            float cur = hbuf[t & 3];
            if (t + 4 < CL) hbuf[t & 3] = __ldg(&Hmat[(segNN + sp[t + 4]) * 64 + d]);
            g_Ah[rowbase + (size_t)t * 64] = run;
            run += swA[t] * cur;
        }
    } else {         // reverse, inclusive suffix of wsuf*h
        float hbuf[4];
#pragma unroll
        for (int i = 0; i < 4; i++) hbuf[i] = __ldg(&Hmat[(segNN + sp[CL - 1 - i]) * 64 + d]);
#pragma unroll 4
        for (int t = 0; t < CL; t++) {
            int q = CL - 1 - t;
            float cur = hbuf[t & 3];
            if (t + 4 < CL) hbuf[t & 3] = __ldg(&Hmat[(segNN + sp[q - 4]) * 64 + d]);
            run += swB[q] * cur;
            g_Bh[rowbase + (size_t)q * 64] = run;
        }
    }
}

// shared combine math: returns attention output element (pre-activation)
__device__ __forceinline__ float combine_elem(int seg, int n, int d) {
    float s1v  = g_s1[seg * NN + n];
    float smax = g_smax[seg];
    float u = s1v + smax;
    float m = (u >= 0.f) ? u : ALPHA_ * u;
    float f1 = expf(u - m);
    float f2 = expf(ALPHA_ * u - m);
    float tau = -s1v;
    const float* srt = g_sorted + seg * NN;
    int lo = 0, hi = NN;
    while (lo < hi) {
        int mid = (lo + hi) >> 1;
        if (__ldg(srt + mid) < tau) lo = mid + 1; else hi = mid;
    }
    int p = lo;
    size_t rb = ((size_t)seg * (NN + 1) + p) * 64 + d;
    float Ahv = g_Ah[rb];
    float Bhv = g_Bh[rb];
    float A1v = g_A1[seg * (NN + 1) + p];
    float B1v = g_B1[seg * (NN + 1) + p];
    float num = f1 * Bhv + f2 * Ahv;
    float den = f1 * B1v + f2 * A1v;
    return num / den;
}

// ---------------- layer-1 combine: elu -> XC ----------------
__global__ __launch_bounds__(256)
void combine1_kernel() {
    const int seg = blockIdx.y, tid = threadIdx.x;
    const int n = blockIdx.x * 4 + (tid >> 6);
    const int d = tid & 63;
    float o = combine_elem(seg, n, d);
    o = (o > 0.f) ? o : expm1f(o);
    int g = seg >> 2, h = seg & 3;
    g_XC[((size_t)g * NN + n) * (HH * DD) + h * DD + d] = o;
}

// ---------------- layer-2 combine: elu -> log_softmax -> out ----------------
__global__ __launch_bounds__(256)
void combine2_kernel(float* __restrict__ out) {
    const int seg = blockIdx.y, tid = threadIdx.x;
    const int n = blockIdx.x * 4 + (tid >> 6);
    const int d = tid & 63;
    float o = combine_elem(seg, n, d);
    o = (o > 0.f) ? o : expm1f(o);

    const int rl = tid >> 6;
    const int lane = tid & 31;
    const int wh = (tid >> 5) & 1;
    __shared__ float smx[4][2], ssm[4][2];

    float m = o;
#pragma unroll
    for (int off = 16; off; off >>= 1) m = fmaxf(m, __shfl_xor_sync(0xffffffffu, m, off));
    if (lane == 0) smx[rl][wh] = m;
    __syncthreads();
    float mx = fmaxf(smx[rl][0], smx[rl][1]);
    float e = expf(o - mx);
    float s = e;
#pragma unroll
    for (int off = 16; off; off >>= 1) s += __shfl_xor_sync(0xffffffffu, s, off);
    if (lane == 0) ssm[rl][wh] = s;
    __syncthreads();
    float tot = ssm[rl][0] + ssm[rl][1];

    out[((size_t)seg * NN + n) * DD + d] = o - mx - logf(tot);
}

// ---------------- launch ----------------
extern "C" void kernel_launch(void* const* d_in, const int* in_sizes, int n_in,
                              void* d_out, int out_size) {
    const float* h_states = (const float*)d_in[0];
    const float* W_heads  = (const float*)d_in[1];
    const float* a_heads  = (const float*)d_in[2];
    const float* W_out    = (const float*)d_in[3];
    const float* a_out    = (const float*)d_in[4];
    float* out = (float*)d_out;

    // ---- layer 1 (per graph, per head) ----
    gemm_kernel<<<dim3(BB * NN / 64, HH), 256>>>(h_states, W_heads, a_heads, 64, HH, 0, 1);
    sort_kernel<<<SEG1, 1024>>>();
    pass3a_kernel<<<dim3(SEG1, CH), 128>>>(1);
    pass3b_kernel<<<SEG1, 256>>>();
    pass3c_kernel<<<dim3(SEG1, CH), 128>>>(1);
    combine1_kernel<<<dim3(NN / 4, SEG1), 256>>>();

    // ---- layer 2 (per graph) ----
    gemm_kernel<<<dim3(BB * NN / 64, 1), 256>>>(nullptr, W_out, a_out, 256, 1, 1, 2);
    sort_kernel<<<BB, 1024>>>();
    pass3a_kernel<<<dim3(BB, CH), 128>>>(2);
    pass3b_kernel<<<BB, 256>>>();
    pass3c_kernel<<<dim3(BB, CH), 128>>>(2);
    combine2_kernel<<<dim3(NN / 4, BB), 256>>>(out);
}

// round 7
// speedup vs baseline: 1.5313x; 1.0017x over previous
#include <cuda_runtime.h>
#include <math.h>

#define NN   2048
#define BB   8
#define HH   4
#define DD   64
#define SEG1 (BB*HH)     // 32 segments in layer 1
#define CH   32          // scan chunks per segment
#define CL   (NN/CH)     // 64 elements per chunk
#define ALPHA_ 0.2f

// ---------------- scratch (static __device__, no allocation) ----------------
__device__ float g_Hbuf [SEG1 * NN * DD];            // layer-1 per-head h (pre-attention)
__device__ float g_H2   [BB   * NN * DD];            // layer-2 h
__device__ float g_s1   [SEG1 * NN];
__device__ float g_s2   [SEG1 * NN];
__device__ float g_sorted[SEG1 * NN];
__device__ int   g_perm [SEG1 * NN];
__device__ float g_wpre [SEG1 * NN];                 // e^{alpha*(s2-s2max)} sorted order
__device__ float g_wsuf [SEG1 * NN];                 // e^{(s2-s2max)} sorted order
__device__ float g_smax [SEG1];
__device__ float g_CT   [SEG1 * CH * 128];           // chunk totals / offsets
__device__ float g_A1   [SEG1 * (NN+1)];             // scalar prefix of wpre
__device__ float g_B1   [SEG1 * (NN+1)];             // scalar SUFFIX of wsuf
__device__ float g_Ah   [SEG1 * (NN+1) * DD];        // vector prefix of wpre*h
__device__ float g_Bh   [SEG1 * (NN+1) * DD];        // vector SUFFIX of wsuf*h
__device__ float g_XC   [BB * NN * HH * DD];         // concat of elu(head outputs)

// ---------------- GEMM: Hout = X @ W[head], plus s1 = h@a[:64], s2 = h@a[64:] ----------------
__global__ __launch_bounds__(256)
void gemm_kernel(const float* __restrict__ Xin,
                 const float* __restrict__ Wmat,
                 const float* __restrict__ avec,
                 int K, int Hcount, int xsel, int layer) {
    __shared__ float XsT[64][68];   // [k][r], padded
    __shared__ float Ws [64][64];   // [k][d]
    const float* X    = xsel ? g_XC : Xin;
    float*       Hout = (layer == 1) ? g_Hbuf : g_H2;

    const int tid  = threadIdx.x;
    const int head = blockIdx.y;
    const int R0   = blockIdx.x * 64;
    const int rq   = tid >> 4;
    const int cq   = tid & 15;

    float acc[4][4];
#pragma unroll
    for (int i = 0; i < 4; i++)
#pragma unroll
        for (int j = 0; j < 4; j++) acc[i][j] = 0.f;

    for (int kp = 0; kp < K; kp += 64) {
        __syncthreads();
#pragma unroll
        for (int i = 0; i < 16; i++) {
            int idx = tid + i * 256;
            int r = idx >> 6, k = idx & 63;
            XsT[k][r] = X[(size_t)(R0 + r) * K + kp + k];
        }
#pragma unroll
        for (int i = 0; i < 16; i++) {
            int idx = tid + i * 256;
            int k = idx >> 6, d = idx & 63;
            Ws[k][d] = Wmat[((size_t)head * K + kp + k) * 64 + d];
        }
        __syncthreads();
#pragma unroll 16
        for (int k = 0; k < 64; k++) {
            float4 xv = *(const float4*)&XsT[k][rq * 4];
            float4 wv = *(const float4*)&Ws [k][cq * 4];
            acc[0][0] += xv.x*wv.x; acc[0][1] += xv.x*wv.y; acc[0][2] += xv.x*wv.z; acc[0][3] += xv.x*wv.w;
            acc[1][0] += xv.y*wv.x; acc[1][1] += xv.y*wv.y; acc[1][2] += xv.y*wv.z; acc[1][3] += xv.y*wv.w;
            acc[2][0] += xv.z*wv.x; acc[2][1] += xv.z*wv.y; acc[2][2] += xv.z*wv.z; acc[2][3] += xv.z*wv.w;
            acc[3][0] += xv.w*wv.x; acc[3][1] += xv.w*wv.y; acc[3][2] += xv.w*wv.z; acc[3][3] += xv.w*wv.w;
        }
    }

    float a1v[4], a2v[4];
#pragma unroll
    for (int j = 0; j < 4; j++) {
        a1v[j] = __ldg(&avec[head * 128 + cq * 4 + j]);
        a2v[j] = __ldg(&avec[head * 128 + 64 + cq * 4 + j]);
    }

#pragma unroll
    for (int i = 0; i < 4; i++) {
        int R = R0 + rq * 4 + i;
        int g = R >> 11;
        int n = R & (NN - 1);
        int seg = g * Hcount + head;
        size_t base = ((size_t)seg * NN + n) * 64 + cq * 4;
        float4 v; v.x = acc[i][0]; v.y = acc[i][1]; v.z = acc[i][2]; v.w = acc[i][3];
        *(float4*)&Hout[base] = v;

        float p1 = acc[i][0]*a1v[0] + acc[i][1]*a1v[1] + acc[i][2]*a1v[2] + acc[i][3]*a1v[3];
        float p2 = acc[i][0]*a2v[0] + acc[i][1]*a2v[1] + acc[i][2]*a2v[2] + acc[i][3]*a2v[3];
#pragma unroll
        for (int off = 8; off; off >>= 1) {
            p1 += __shfl_down_sync(0xffffffffu, p1, off, 16);
            p2 += __shfl_down_sync(0xffffffffu, p2, off, 16);
        }
        if (cq == 0) {
            g_s1[seg * NN + n] = p1;
            g_s2[seg * NN + n] = p2;
        }
    }
}

// ---------------- bitonic sort: 1024 threads, exactly one comparator each ----------------
__global__ __launch_bounds__(1024)
void sort_kernel() {
    __shared__ float key[NN];
    __shared__ int   idx[NN];
    const int seg = blockIdx.x, tid = threadIdx.x;

    key[tid]        = g_s2[seg * NN + tid];        idx[tid]        = tid;
    key[tid + 1024] = g_s2[seg * NN + tid + 1024]; idx[tid + 1024] = tid + 1024;

    for (int k = 2; k <= NN; k <<= 1) {
        for (int j = k >> 1; j > 0; j >>= 1) {
            __syncthreads();
            int i = ((tid & ~(j - 1)) << 1) | (tid & (j - 1));
            int p = i | j;
            bool up = ((i & k) == 0);
            float ka = key[i], kb = key[p];
            if ((ka > kb) == up) {
                key[i] = kb; key[p] = ka;
                int t = idx[i]; idx[i] = idx[p]; idx[p] = t;
            }
        }
    }
    __syncthreads();

    float smaxv = key[NN - 1];
#pragma unroll
    for (int u = 0; u < 2; u++) {
        int i = tid + u * 1024;
        float kk = key[i];
        g_sorted[seg * NN + i] = kk;
        g_perm  [seg * NN + i] = idx[i];
        g_wsuf  [seg * NN + i] = expf(kk - smaxv);
        g_wpre  [seg * NN + i] = expf(ALPHA_ * (kk - smaxv));
    }
    if (tid == 0) g_smax[seg] = smaxv;
}

// ---------------- pass 3a: per-chunk vector sums (staged indices, high MLP) ----------------
__global__ __launch_bounds__(128)
void pass3a_kernel(int layer) {
    const int seg = blockIdx.x, c = blockIdx.y, tid = threadIdx.x;
    const float* Hmat = (layer == 1) ? g_Hbuf : g_H2;
    const int d = tid & 63;
    const int q0 = c * CL;

    __shared__ int   sp[CL];
    __shared__ float swA[CL], swB[CL];
    if (tid < CL) {
        sp[tid] = g_perm[seg * NN + q0 + tid];
    } else {
        int q = tid - 64;                         // CL == 64
        swA[q] = g_wpre[seg * NN + q0 + q];
        swB[q] = g_wsuf[seg * NN + q0 + q];
    }
    __syncthreads();

    const float* sw = (tid < 64) ? swA : swB;
    const size_t segNN = (size_t)seg * NN;
    float acc = 0.f;
#pragma unroll 8
    for (int q = 0; q < CL; q++) {
        acc += sw[q] * __ldg(&Hmat[(segNN + sp[q]) * 64 + d]);
    }
    g_CT[(seg * CH + c) * 128 + tid] = acc;
}

// ---------------- pass 3b: parallel scans (register chunk scan + warp shuffle scans) ----------------
__global__ __launch_bounds__(256)
void pass3b_kernel() {
    const int seg = blockIdx.x, tid = threadIdx.x;
    const int lane = tid & 31, wid = tid >> 5;
    __shared__ float wsumA[8], wsumB[8], woffA[8], woffB[8];

    // (a) vector chunk offsets: load all CH values, scan in registers
    if (tid < 128) {
        float v[CH];
#pragma unroll
        for (int c = 0; c < CH; c++) v[c] = g_CT[(seg * CH + c) * 128 + tid];
        if (tid < 64) {
            float run = 0.f;
#pragma unroll
            for (int c = 0; c < CH; c++) { float t = v[c]; g_CT[(seg * CH + c) * 128 + tid] = run; run += t; }
            g_Ah[((size_t)seg * (NN + 1) + NN) * 64 + tid] = run;
        } else {
            float run = 0.f;
#pragma unroll
            for (int c = CH - 1; c >= 0; c--) { float t = v[c]; g_CT[(seg * CH + c) * 128 + tid] = run; run += t; }
            g_Bh[((size_t)seg * (NN + 1) + NN) * 64 + (tid - 64)] = 0.f;
        }
    }

    // (b) scalar scans: A1 = exclusive prefix of wpre, B1 = inclusive suffix of wsuf
    const int qb = tid * 8;
    float wa[8], wb[8];
    {
        float4 t0 = *(const float4*)&g_wpre[seg * NN + qb];
        float4 t1 = *(const float4*)&g_wpre[seg * NN + qb + 4];
        wa[0]=t0.x; wa[1]=t0.y; wa[2]=t0.z; wa[3]=t0.w;
        wa[4]=t1.x; wa[5]=t1.y; wa[6]=t1.z; wa[7]=t1.w;
        float4 u0 = *(const float4*)&g_wsuf[seg * NN + qb];
        float4 u1 = *(const float4*)&g_wsuf[seg * NN + qb + 4];
        wb[0]=u0.x; wb[1]=u0.y; wb[2]=u0.z; wb[3]=u0.w;
        wb[4]=u1.x; wb[5]=u1.y; wb[6]=u1.z; wb[7]=u1.w;
    }
    float la[8], lb[8];
    float sa = 0.f;
#pragma unroll
    for (int i = 0; i < 8; i++) { la[i] = sa; sa += wa[i]; }
    float sb = 0.f;
#pragma unroll
    for (int i = 7; i >= 0; i--) { sb += wb[i]; lb[i] = sb; }

    // warp inclusive prefix scan of sa
    float xa = sa;
#pragma unroll
    for (int off = 1; off < 32; off <<= 1) {
        float y = __shfl_up_sync(0xffffffffu, xa, off);
        if (lane >= off) xa += y;
    }
    float exA = xa - sa;
    // warp inclusive suffix scan of sb
    float xb = sb;
#pragma unroll
    for (int off = 1; off < 32; off <<= 1) {
        float y = __shfl_down_sync(0xffffffffu, xb, off);
        if (lane < 32 - off) xb += y;
    }
    float exB = xb - sb;

    if (lane == 31) wsumA[wid] = xa;
    if (lane == 0)  wsumB[wid] = xb;
    __syncthreads();
    if (tid == 0) {
        float r = 0.f;
        for (int w = 0; w < 8; w++) { float t = wsumA[w]; woffA[w] = r; r += t; }
        g_A1[seg * (NN + 1) + NN] = r;
        r = 0.f;
        for (int w = 7; w >= 0; w--) { float t = wsumB[w]; woffB[w] = r; r += t; }
        g_B1[seg * (NN + 1) + NN] = 0.f;
    }
    __syncthreads();
    float oa = woffA[wid] + exA, ob = woffB[wid] + exB;
#pragma unroll
    for (int i = 0; i < 8; i++) {
        g_A1[seg * (NN + 1) + qb + i] = oa + la[i];
        g_B1[seg * (NN + 1) + qb + i] = ob + lb[i];
    }
}

// ---------------- pass 3c: full vector prefix/suffix arrays (depth-4 prefetch pipeline) ----------------
__global__ __launch_bounds__(128)
void pass3c_kernel(int layer) {
    const int seg = blockIdx.x, c = blockIdx.y, tid = threadIdx.x;
    const float* __restrict__ Hmat = (layer == 1) ? g_Hbuf : g_H2;
    const int d = tid & 63;
    const int q0 = c * CL;

    __shared__ int   sp[CL];
    __shared__ float swA[CL], swB[CL];
    if (tid < CL) {
        sp[tid] = g_perm[seg * NN + q0 + tid];
    } else {
        int q = tid - 64;
        swA[q] = g_wpre[seg * NN + q0 + q];
        swB[q] = g_wsuf[seg * NN + q0 + q];
    }
    __syncthreads();

    const size_t segNN = (size_t)seg * NN;
    const size_t rowbase = ((size_t)seg * (NN + 1) + q0) * 64 + d;
    float run = g_CT[(seg * CH + c) * 128 + tid];

    if (tid < 64) {  // forward, exclusive prefix of wpre*h
        float hbuf[4];
#pragma unroll
        for (int i = 0; i < 4; i++) hbuf[i] = __ldg(&Hmat[(segNN + sp[i]) * 64 + d]);
#pragma unroll 4
        for (int t = 0; t < CL; t++) {
            float cur = hbuf[t & 3];
            if (t + 4 < CL) hbuf[t & 3] = __ldg(&Hmat[(segNN + sp[t + 4]) * 64 + d]);
            g_Ah[rowbase + (size_t)t * 64] = run;
            run += swA[t] * cur;
        }
    } else {         // reverse, inclusive suffix of wsuf*h
        float hbuf[4];
#pragma unroll
        for (int i = 0; i < 4; i++) hbuf[i] = __ldg(&Hmat[(segNN + sp[CL - 1 - i]) * 64 + d]);
#pragma unroll 4
        for (int t = 0; t < CL; t++) {
            int q = CL - 1 - t;
            float cur = hbuf[t & 3];
            if (t + 4 < CL) hbuf[t & 3] = __ldg(&Hmat[(segNN + sp[q - 4]) * 64 + d]);
            run += swB[q] * cur;
            g_Bh[rowbase + (size_t)q * 64] = run;
        }
    }
}

// shared combine math: returns attention output element (pre-activation)
__device__ __forceinline__ float combine_elem(int seg, int n, int d) {
    float s1v  = g_s1[seg * NN + n];
    float smax = g_smax[seg];
    float u = s1v + smax;
    float m = (u >= 0.f) ? u : ALPHA_ * u;
    float f1 = expf(u - m);
    float f2 = expf(ALPHA_ * u - m);
    float tau = -s1v;
    const float* srt = g_sorted + seg * NN;
    int lo = 0, hi = NN;
    while (lo < hi) {
        int mid = (lo + hi) >> 1;
        if (__ldg(srt + mid) < tau) lo = mid + 1; else hi = mid;
    }
    int p = lo;
    size_t rb = ((size_t)seg * (NN + 1) + p) * 64 + d;
    float Ahv = g_Ah[rb];
    float Bhv = g_Bh[rb];
    float A1v = g_A1[seg * (NN + 1) + p];
    float B1v = g_B1[seg * (NN + 1) + p];
    float num = f1 * Bhv + f2 * Ahv;
    float den = f1 * B1v + f2 * A1v;
    return num / den;
}

// ---------------- layer-1 combine: elu -> XC ----------------
__global__ __launch_bounds__(256)
void combine1_kernel() {
    const int seg = blockIdx.y, tid = threadIdx.x;
    const int n = blockIdx.x * 4 + (tid >> 6);
    const int d = tid & 63;
    float o = combine_elem(seg, n, d);
    o = (o > 0.f) ? o : expm1f(o);
    int g = seg >> 2, h = seg & 3;
    g_XC[((size_t)g * NN + n) * (HH * DD) + h * DD + d] = o;
}

// ---------------- layer-2 combine: elu -> log_softmax -> out ----------------
__global__ __launch_bounds__(256)
void combine2_kernel(float* __restrict__ out) {
    const int seg = blockIdx.y, tid = threadIdx.x;
    const int n = blockIdx.x * 4 + (tid >> 6);
    const int d = tid & 63;
    float o = combine_elem(seg, n, d);
    o = (o > 0.f) ? o : expm1f(o);

    const int rl = tid >> 6;
    const int lane = tid & 31;
    const int wh = (tid >> 5) & 1;
    __shared__ float smx[4][2], ssm[4][2];

    float m = o;
#pragma unroll
    for (int off = 16; off; off >>= 1) m = fmaxf(m, __shfl_xor_sync(0xffffffffu, m, off));
    if (lane == 0) smx[rl][wh] = m;
    __syncthreads();
    float mx = fmaxf(smx[rl][0], smx[rl][1]);
    float e = expf(o - mx);
    float s = e;
#pragma unroll
    for (int off = 16; off; off >>= 1) s += __shfl_xor_sync(0xffffffffu, s, off);
    if (lane == 0) ssm[rl][wh] = s;
    __syncthreads();
    float tot = ssm[rl][0] + ssm[rl][1];

    out[((size_t)seg * NN + n) * DD + d] = o - mx - logf(tot);
}

// ---------------- launch ----------------
extern "C" void kernel_launch(void* const* d_in, const int* in_sizes, int n_in,
                              void* d_out, int out_size) {
    const float* h_states = (const float*)d_in[0];
    const float* W_heads  = (const float*)d_in[1];
    const float* a_heads  = (const float*)d_in[2];
    const float* W_out    = (const float*)d_in[3];
    const float* a_out    = (const float*)d_in[4];
    float* out = (float*)d_out;

    // ---- layer 1 (per graph, per head) ----
    gemm_kernel<<<dim3(BB * NN / 64, HH), 256>>>(h_states, W_heads, a_heads, 64, HH, 0, 1);
    sort_kernel<<<SEG1, 1024>>>();
    pass3a_kernel<<<dim3(SEG1, CH), 128>>>(1);
    pass3b_kernel<<<SEG1, 256>>>();
    pass3c_kernel<<<dim3(SEG1, CH), 128>>>(1);
    combine1_kernel<<<dim3(NN / 4, SEG1), 256>>>();

    // ---- layer 2 (per graph) ----
    gemm_kernel<<<dim3(BB * NN / 64, 1), 256>>>(nullptr, W_out, a_out, 256, 1, 1, 2);
    sort_kernel<<<BB, 1024>>>();
    pass3a_kernel<<<dim3(BB, CH), 128>>>(2);
    pass3b_kernel<<<BB, 256>>>();
    pass3c_kernel<<<dim3(BB, CH), 128>>>(2);
    combine2_kernel<<<dim3(NN / 4, BB), 256>>>(out);
}

// round 8
// speedup vs baseline: 1.8245x; 1.1915x over previous
#include <cuda_runtime.h>
#include <math.h>

#define NN   2048
#define BB   8
#define HH   4
#define DD   64
#define SEG1 (BB*HH)     // 32 segments in layer 1
#define CH   32          // scan chunks per segment
#define CL   (NN/CH)     // 64 elements per chunk
#define ALPHA_ 0.2f

// ---------------- scratch (static __device__, no allocation) ----------------
__device__ float g_Hbuf [SEG1 * NN * DD];
__device__ float g_H2   [BB   * NN * DD];
__device__ float g_s1   [SEG1 * NN];
__device__ float g_s2   [SEG1 * NN];
__device__ float g_sorted[SEG1 * NN];
__device__ int   g_perm [SEG1 * NN];
__device__ float g_wpre [SEG1 * NN];
__device__ float g_wsuf [SEG1 * NN];
__device__ float g_smax [SEG1];
__device__ float g_CT   [SEG1 * CH * 128];
__device__ float g_A1   [SEG1 * (NN+1)];
__device__ float g_B1   [SEG1 * (NN+1)];
__device__ float g_Ah   [SEG1 * (NN+1) * DD];
__device__ float g_Bh   [SEG1 * (NN+1) * DD];
__device__ float g_XC   [BB * NN * HH * DD];
__device__ int   g_qp   [SEG1 * NN];          // split point per query
__device__ float2 g_qr  [SEG1 * NN];          // (rA, rB) = (f2/den, f1/den)

// ---------------- layer-1 GEMM: all 4 heads per block, X tile reused ----------------
__global__ __launch_bounds__(256)
void gemm1_kernel(const float* __restrict__ X,
                  const float* __restrict__ Wmat,
                  const float* __restrict__ avec) {
    __shared__ float XsT[64][68];   // [k][r]
    __shared__ float Ws [64][64];   // [k][d]
    const int tid = threadIdx.x;
    const int R0  = blockIdx.x * 64;
    const int rq  = tid >> 4;
    const int cq  = tid & 15;

    // stage X tile once (K = 64, single panel)
#pragma unroll
    for (int i = 0; i < 16; i++) {
        int idx = tid + i * 256;
        int r = idx >> 6, k = idx & 63;
        XsT[k][r] = X[(size_t)(R0 + r) * 64 + k];
    }

    for (int head = 0; head < HH; head++) {
        __syncthreads();
#pragma unroll
        for (int i = 0; i < 16; i++) {
            int idx = tid + i * 256;
            int k = idx >> 6, d = idx & 63;
            Ws[k][d] = Wmat[((size_t)head * 64 + k) * 64 + d];
        }
        __syncthreads();

        float acc[4][4];
#pragma unroll
        for (int i = 0; i < 4; i++)
#pragma unroll
            for (int j = 0; j < 4; j++) acc[i][j] = 0.f;

#pragma unroll 16
        for (int k = 0; k < 64; k++) {
            float4 xv = *(const float4*)&XsT[k][rq * 4];
            float4 wv = *(const float4*)&Ws [k][cq * 4];
            acc[0][0] += xv.x*wv.x; acc[0][1] += xv.x*wv.y; acc[0][2] += xv.x*wv.z; acc[0][3] += xv.x*wv.w;
            acc[1][0] += xv.y*wv.x; acc[1][1] += xv.y*wv.y; acc[1][2] += xv.y*wv.z; acc[1][3] += xv.y*wv.w;
            acc[2][0] += xv.z*wv.x; acc[2][1] += xv.z*wv.y; acc[2][2] += xv.z*wv.z; acc[2][3] += xv.z*wv.w;
            acc[3][0] += xv.w*wv.x; acc[3][1] += xv.w*wv.y; acc[3][2] += xv.w*wv.z; acc[3][3] += xv.w*wv.w;
        }

        float a1v[4], a2v[4];
#pragma unroll
        for (int j = 0; j < 4; j++) {
            a1v[j] = __ldg(&avec[head * 128 + cq * 4 + j]);
            a2v[j] = __ldg(&avec[head * 128 + 64 + cq * 4 + j]);
        }
#pragma unroll
        for (int i = 0; i < 4; i++) {
            int R = R0 + rq * 4 + i;
            int g = R >> 11;
            int n = R & (NN - 1);
            int seg = g * HH + head;
            size_t base = ((size_t)seg * NN + n) * 64 + cq * 4;
            float4 v; v.x = acc[i][0]; v.y = acc[i][1]; v.z = acc[i][2]; v.w = acc[i][3];
            *(float4*)&g_Hbuf[base] = v;

            float p1 = acc[i][0]*a1v[0] + acc[i][1]*a1v[1] + acc[i][2]*a1v[2] + acc[i][3]*a1v[3];
            float p2 = acc[i][0]*a2v[0] + acc[i][1]*a2v[1] + acc[i][2]*a2v[2] + acc[i][3]*a2v[3];
#pragma unroll
            for (int off = 8; off; off >>= 1) {
                p1 += __shfl_down_sync(0xffffffffu, p1, off, 16);
                p2 += __shfl_down_sync(0xffffffffu, p2, off, 16);
            }
            if (cq == 0) {
                g_s1[seg * NN + n] = p1;
                g_s2[seg * NN + n] = p2;
            }
        }
    }
}

// ---------------- layer-2 GEMM (K = 256) ----------------
__global__ __launch_bounds__(256)
void gemm2_kernel(const float* __restrict__ Wmat,
                  const float* __restrict__ avec) {
    __shared__ float XsT[64][68];
    __shared__ float Ws [64][64];
    const int tid = threadIdx.x;
    const int R0  = blockIdx.x * 64;
    const int rq  = tid >> 4;
    const int cq  = tid & 15;

    float acc[4][4];
#pragma unroll
    for (int i = 0; i < 4; i++)
#pragma unroll
        for (int j = 0; j < 4; j++) acc[i][j] = 0.f;

    for (int kp = 0; kp < 256; kp += 64) {
        __syncthreads();
#pragma unroll
        for (int i = 0; i < 16; i++) {
            int idx = tid + i * 256;
            int r = idx >> 6, k = idx & 63;
            XsT[k][r] = g_XC[(size_t)(R0 + r) * 256 + kp + k];
        }
#pragma unroll
        for (int i = 0; i < 16; i++) {
            int idx = tid + i * 256;
            int k = idx >> 6, d = idx & 63;
            Ws[k][d] = Wmat[((size_t)kp + k) * 64 + d];
        }
        __syncthreads();
#pragma unroll 16
        for (int k = 0; k < 64; k++) {
            float4 xv = *(const float4*)&XsT[k][rq * 4];
            float4 wv = *(const float4*)&Ws [k][cq * 4];
            acc[0][0] += xv.x*wv.x; acc[0][1] += xv.x*wv.y; acc[0][2] += xv.x*wv.z; acc[0][3] += xv.x*wv.w;
            acc[1][0] += xv.y*wv.x; acc[1][1] += xv.y*wv.y; acc[1][2] += xv.y*wv.z; acc[1][3] += xv.y*wv.w;
            acc[2][0] += xv.z*wv.x; acc[2][1] += xv.z*wv.y; acc[2][2] += xv.z*wv.z; acc[2][3] += xv.z*wv.w;
            acc[3][0] += xv.w*wv.x; acc[3][1] += xv.w*wv.y; acc[3][2] += xv.w*wv.z; acc[3][3] += xv.w*wv.w;
        }
    }

    float a1v[4], a2v[4];
#pragma unroll
    for (int j = 0; j < 4; j++) {
        a1v[j] = __ldg(&avec[cq * 4 + j]);
        a2v[j] = __ldg(&avec[64 + cq * 4 + j]);
    }
#pragma unroll
    for (int i = 0; i < 4; i++) {
        int R = R0 + rq * 4 + i;
        int seg = R >> 11;
        int n = R & (NN - 1);
        size_t base = ((size_t)seg * NN + n) * 64 + cq * 4;
        float4 v; v.x = acc[i][0]; v.y = acc[i][1]; v.z = acc[i][2]; v.w = acc[i][3];
        *(float4*)&g_H2[base] = v;

        float p1 = acc[i][0]*a1v[0] + acc[i][1]*a1v[1] + acc[i][2]*a1v[2] + acc[i][3]*a1v[3];
        float p2 = acc[i][0]*a2v[0] + acc[i][1]*a2v[1] + acc[i][2]*a2v[2] + acc[i][3]*a2v[3];
#pragma unroll
        for (int off = 8; off; off >>= 1) {
            p1 += __shfl_down_sync(0xffffffffu, p1, off, 16);
            p2 += __shfl_down_sync(0xffffffffu, p2, off, 16);
        }
        if (cq == 0) {
            g_s1[seg * NN + n] = p1;
            g_s2[seg * NN + n] = p2;
        }
    }
}

// ---------------- bitonic sort: 1024 threads, one comparator each ----------------
__global__ __launch_bounds__(1024)
void sort_kernel() {
    __shared__ float key[NN];
    __shared__ int   idx[NN];
    const int seg = blockIdx.x, tid = threadIdx.x;

    key[tid]        = g_s2[seg * NN + tid];        idx[tid]        = tid;
    key[tid + 1024] = g_s2[seg * NN + tid + 1024]; idx[tid + 1024] = tid + 1024;

    for (int k = 2; k <= NN; k <<= 1) {
        for (int j = k >> 1; j > 0; j >>= 1) {
            __syncthreads();
            int i = ((tid & ~(j - 1)) << 1) | (tid & (j - 1));
            int p = i | j;
            bool up = ((i & k) == 0);
            float ka = key[i], kb = key[p];
            if ((ka > kb) == up) {
                key[i] = kb; key[p] = ka;
                int t = idx[i]; idx[i] = idx[p]; idx[p] = t;
            }
        }
    }
    __syncthreads();

    float smaxv = key[NN - 1];
#pragma unroll
    for (int u = 0; u < 2; u++) {
        int i = tid + u * 1024;
        float kk = key[i];
        g_sorted[seg * NN + i] = kk;
        g_perm  [seg * NN + i] = idx[i];
        g_wsuf  [seg * NN + i] = expf(kk - smaxv);
        g_wpre  [seg * NN + i] = expf(ALPHA_ * (kk - smaxv));
    }
    if (tid == 0) g_smax[seg] = smaxv;
}

// ---------------- pass 3a: per-chunk sums, BOTH halves per thread (one H load) ----------------
__global__ __launch_bounds__(64)
void pass3a_kernel(int layer) {
    const int seg = blockIdx.x, c = blockIdx.y, d = threadIdx.x;
    const float* __restrict__ Hmat = (layer == 1) ? g_Hbuf : g_H2;
    const int q0 = c * CL;

    __shared__ int   sp[CL];
    __shared__ float swA[CL], swB[CL];
    sp [d] = g_perm[seg * NN + q0 + d];
    swA[d] = g_wpre[seg * NN + q0 + d];
    swB[d] = g_wsuf[seg * NN + q0 + d];
    __syncthreads();

    const size_t segNN = (size_t)seg * NN;
    float accA = 0.f, accB = 0.f;
#pragma unroll 8
    for (int q = 0; q < CL; q++) {
        float h = __ldg(&Hmat[(segNN + sp[q]) * 64 + d]);
        accA += swA[q] * h;
        accB += swB[q] * h;
    }
    g_CT[(seg * CH + c) * 128 + d]      = accA;
    g_CT[(seg * CH + c) * 128 + 64 + d] = accB;
}

// ---------------- pass 3b: chunk-offset scan + scalar scans ----------------
__global__ __launch_bounds__(256)
void pass3b_kernel() {
    const int seg = blockIdx.x, tid = threadIdx.x;
    const int lane = tid & 31, wid = tid >> 5;
    __shared__ float wsumA[8], wsumB[8], woffA[8], woffB[8];

    if (tid < 128) {
        float v[CH];
#pragma unroll
        for (int c = 0; c < CH; c++) v[c] = g_CT[(seg * CH + c) * 128 + tid];
        if (tid < 64) {
            float run = 0.f;
#pragma unroll
            for (int c = 0; c < CH; c++) { float t = v[c]; g_CT[(seg * CH + c) * 128 + tid] = run; run += t; }
            g_Ah[((size_t)seg * (NN + 1) + NN) * 64 + tid] = run;
        } else {
            float run = 0.f;
#pragma unroll
            for (int c = CH - 1; c >= 0; c--) { float t = v[c]; g_CT[(seg * CH + c) * 128 + tid] = run; run += t; }
            g_Bh[((size_t)seg * (NN + 1) + NN) * 64 + (tid - 64)] = 0.f;
        }
    }

    const int qb = tid * 8;
    float wa[8], wb[8];
    {
        float4 t0 = *(const float4*)&g_wpre[seg * NN + qb];
        float4 t1 = *(const float4*)&g_wpre[seg * NN + qb + 4];
        wa[0]=t0.x; wa[1]=t0.y; wa[2]=t0.z; wa[3]=t0.w;
        wa[4]=t1.x; wa[5]=t1.y; wa[6]=t1.z; wa[7]=t1.w;
        float4 u0 = *(const float4*)&g_wsuf[seg * NN + qb];
        float4 u1 = *(const float4*)&g_wsuf[seg * NN + qb + 4];
        wb[0]=u0.x; wb[1]=u0.y; wb[2]=u0.z; wb[3]=u0.w;
        wb[4]=u1.x; wb[5]=u1.y; wb[6]=u1.z; wb[7]=u1.w;
    }
    float la[8], lb[8];
    float sa = 0.f;
#pragma unroll
    for (int i = 0; i < 8; i++) { la[i] = sa; sa += wa[i]; }
    float sb = 0.f;
#pragma unroll
    for (int i = 7; i >= 0; i--) { sb += wb[i]; lb[i] = sb; }

    float xa = sa;
#pragma unroll
    for (int off = 1; off < 32; off <<= 1) {
        float y = __shfl_up_sync(0xffffffffu, xa, off);
        if (lane >= off) xa += y;
    }
    float exA = xa - sa;
    float xb = sb;
#pragma unroll
    for (int off = 1; off < 32; off <<= 1) {
        float y = __shfl_down_sync(0xffffffffu, xb, off);
        if (lane < 32 - off) xb += y;
    }
    float exB = xb - sb;

    if (lane == 31) wsumA[wid] = xa;
    if (lane == 0)  wsumB[wid] = xb;
    __syncthreads();
    if (tid == 0) {
        float r = 0.f;
        for (int w = 0; w < 8; w++) { float t = wsumA[w]; woffA[w] = r; r += t; }
        g_A1[seg * (NN + 1) + NN] = r;
        r = 0.f;
        for (int w = 7; w >= 0; w--) { float t = wsumB[w]; woffB[w] = r; r += t; }
        g_B1[seg * (NN + 1) + NN] = 0.f;
    }
    __syncthreads();
    float oa = woffA[wid] + exA, ob = woffB[wid] + exB;
#pragma unroll
    for (int i = 0; i < 8; i++) {
        g_A1[seg * (NN + 1) + qb + i] = oa + la[i];
        g_B1[seg * (NN + 1) + qb + i] = ob + lb[i];
    }
}

// ---------------- pass 3c: smem-staged tile, both scan directions ----------------
__global__ __launch_bounds__(128)
void pass3c_kernel(int layer) {
    const int seg = blockIdx.x, c = blockIdx.y, tid = threadIdx.x;
    const float* __restrict__ Hmat = (layer == 1) ? g_Hbuf : g_H2;
    const int q0 = c * CL;

    __shared__ int   sp[CL];
    __shared__ float swA[CL], swB[CL];
    __shared__ float tile[CL * 64];     // tile[q*64 + d]

    if (tid < 64) {
        sp [tid] = g_perm[seg * NN + q0 + tid];
        swA[tid] = g_wpre[seg * NN + q0 + tid];
    } else {
        swB[tid - 64] = g_wsuf[seg * NN + q0 + tid - 64];
    }
    __syncthreads();

    const size_t segNN = (size_t)seg * NN;
#pragma unroll
    for (int i = 0; i < 32; i++) {
        int lin = tid + 128 * i;
        int q = lin >> 6, d = lin & 63;
        tile[lin] = __ldg(&Hmat[(segNN + sp[q]) * 64 + d]);
    }
    __syncthreads();

    const int d = tid & 63;
    const size_t rowbase = ((size_t)seg * (NN + 1) + q0) * 64 + d;
    float run = g_CT[(seg * CH + c) * 128 + tid];

    if (tid < 64) {  // forward exclusive prefix of wpre*h
#pragma unroll 8
        for (int t = 0; t < CL; t++) {
            g_Ah[rowbase + (size_t)t * 64] = run;
            run += swA[t] * tile[t * 64 + d];
        }
    } else {         // reverse inclusive suffix of wsuf*h
#pragma unroll 8
        for (int t = CL - 1; t >= 0; t--) {
            run += swB[t] * tile[t * 64 + d];
            g_Bh[rowbase + (size_t)t * 64] = run;
        }
    }
}

// ---------------- qprep: one binary search + factor precompute per query ----------------
__global__ __launch_bounds__(256)
void qprep_kernel() {
    const int seg = blockIdx.x, tid = threadIdx.x;
    const int n = blockIdx.y * 256 + tid;

    __shared__ float srt[NN];
#pragma unroll
    for (int i = 0; i < 8; i++) srt[tid + 256 * i] = g_sorted[seg * NN + tid + 256 * i];
    __syncthreads();

    float s1v  = g_s1[seg * NN + n];
    float smax = g_smax[seg];
    float u = s1v + smax;
    float m = (u >= 0.f) ? u : ALPHA_ * u;
    float f1 = expf(u - m);
    float f2 = expf(ALPHA_ * u - m);
    float tau = -s1v;
    int lo = 0, hi = NN;
    while (lo < hi) {
        int mid = (lo + hi) >> 1;
        if (srt[mid] < tau) lo = mid + 1; else hi = mid;
    }
    int p = lo;
    float A1v = __ldg(&g_A1[seg * (NN + 1) + p]);
    float B1v = __ldg(&g_B1[seg * (NN + 1) + p]);
    float den = f1 * B1v + f2 * A1v;
    g_qp[seg * NN + n] = p;
    g_qr[seg * NN + n] = make_float2(f2 / den, f1 / den);
}

// ---------------- layer-1 combine: pure stream, elu -> XC ----------------
__global__ __launch_bounds__(256)
void combine1_kernel() {
    const int seg = blockIdx.y, tid = threadIdx.x;
    const int n  = blockIdx.x * 16 + (tid >> 4);
    const int d4 = (tid & 15) * 4;

    int    p = g_qp[seg * NN + n];
    float2 r = g_qr[seg * NN + n];
    size_t rb = ((size_t)seg * (NN + 1) + p) * 64 + d4;
    float4 a = *(const float4*)&g_Ah[rb];
    float4 b = *(const float4*)&g_Bh[rb];
    float4 o;
    o.x = r.y * b.x + r.x * a.x;
    o.y = r.y * b.y + r.x * a.y;
    o.z = r.y * b.z + r.x * a.z;
    o.w = r.y * b.w + r.x * a.w;
    o.x = (o.x > 0.f) ? o.x : expm1f(o.x);
    o.y = (o.y > 0.f) ? o.y : expm1f(o.y);
    o.z = (o.z > 0.f) ? o.z : expm1f(o.z);
    o.w = (o.w > 0.f) ? o.w : expm1f(o.w);

    int g = seg >> 2, h = seg & 3;
    *(float4*)&g_XC[((size_t)g * NN + n) * (HH * DD) + h * DD + d4] = o;
}

// ---------------- layer-2 combine: stream, elu -> log_softmax -> out ----------------
__global__ __launch_bounds__(256)
void combine2_kernel(float* __restrict__ out) {
    const int seg = blockIdx.y, tid = threadIdx.x;
    const int n  = blockIdx.x * 16 + (tid >> 4);
    const int d4 = (tid & 15) * 4;

    int    p = g_qp[seg * NN + n];
    float2 r = g_qr[seg * NN + n];
    size_t rb = ((size_t)seg * (NN + 1) + p) * 64 + d4;
    float4 a = *(const float4*)&g_Ah[rb];
    float4 b = *(const float4*)&g_Bh[rb];
    float4 o;
    o.x = r.y * b.x + r.x * a.x;
    o.y = r.y * b.y + r.x * a.y;
    o.z = r.y * b.z + r.x * a.z;
    o.w = r.y * b.w + r.x * a.w;
    o.x = (o.x > 0.f) ? o.x : expm1f(o.x);
    o.y = (o.y > 0.f) ? o.y : expm1f(o.y);
    o.z = (o.z > 0.f) ? o.z : expm1f(o.z);
    o.w = (o.w > 0.f) ? o.w : expm1f(o.w);

    // log_softmax over 64 dims: 16 lanes per row, 4 elems per lane
    float lm = fmaxf(fmaxf(o.x, o.y), fmaxf(o.z, o.w));
#pragma unroll
    for (int off = 8; off; off >>= 1)
        lm = fmaxf(lm, __shfl_xor_sync(0xffffffffu, lm, off, 16));
    float ls = expf(o.x - lm) + expf(o.y - lm) + expf(o.z - lm) + expf(o.w - lm);
#pragma unroll
    for (int off = 8; off; off >>= 1)
        ls += __shfl_xor_sync(0xffffffffu, ls, off, 16);
    float sub = lm + logf(ls);

    float4 w;
    w.x = o.x - sub; w.y = o.y - sub; w.z = o.z - sub; w.w = o.w - sub;
    *(float4*)&out[((size_t)seg * NN + n) * DD + d4] = w;
}

// ---------------- launch ----------------
extern "C" void kernel_launch(void* const* d_in, const int* in_sizes, int n_in,
                              void* d_out, int out_size) {
    const float* h_states = (const float*)d_in[0];
    const float* W_heads  = (const float*)d_in[1];
    const float* a_heads  = (const float*)d_in[2];
    const float* W_out    = (const float*)d_in[3];
    const float* a_out    = (const float*)d_in[4];
    float* out = (float*)d_out;

    // ---- layer 1 ----
    gemm1_kernel<<<BB * NN / 64, 256>>>(h_states, W_heads, a_heads);
    sort_kernel<<<SEG1, 1024>>>();
    pass3a_kernel<<<dim3(SEG1, CH), 64>>>(1);
    pass3b_kernel<<<SEG1, 256>>>();
    pass3c_kernel<<<dim3(SEG1, CH), 128>>>(1);
    qprep_kernel<<<dim3(SEG1, NN / 256), 256>>>();
    combine1_kernel<<<dim3(NN / 16, SEG1), 256>>>();

    // ---- layer 2 ----
    gemm2_kernel<<<BB * NN / 64, 256>>>(W_out, a_out);
    sort_kernel<<<BB, 1024>>>();
    pass3a_kernel<<<dim3(BB, CH), 64>>>(2);
    pass3b_kernel<<<BB, 256>>>();
    pass3c_kernel<<<dim3(BB, CH), 128>>>(2);
    qprep_kernel<<<dim3(BB, NN / 256), 256>>>();
    combine2_kernel<<<dim3(NN / 16, BB), 256>>>(out);
}

// round 9
// speedup vs baseline: 1.8480x; 1.0128x over previous
#include <cuda_runtime.h>
#include <math.h>

#define NN   2048
#define BB   8
#define HH   4
#define DD   64
#define SEG1 (BB*HH)     // 32 segments in layer 1
#define CH   32          // scan chunks per segment
#define CL   (NN/CH)     // 64 elements per chunk
#define ALPHA_ 0.2f

// ---------------- scratch (static __device__, no allocation) ----------------
__device__ float g_Hbuf [SEG1 * NN * DD];
__device__ float g_H2   [BB   * NN * DD];
__device__ float g_s1   [SEG1 * NN];
__device__ float g_s2   [SEG1 * NN];
__device__ float g_sorted[SEG1 * NN];
__device__ int   g_perm [SEG1 * NN];
__device__ float g_wpre [SEG1 * NN];
__device__ float g_wsuf [SEG1 * NN];
__device__ float g_smax [SEG1];
__device__ float g_CT   [SEG1 * CH * 128];
__device__ float g_A1   [SEG1 * (NN+1)];
__device__ float g_B1   [SEG1 * (NN+1)];
__device__ float g_Ah   [SEG1 * (NN+1) * DD];
__device__ float g_Bh   [SEG1 * (NN+1) * DD];
__device__ float g_XC   [BB * NN * HH * DD];
__device__ int   g_qp   [SEG1 * NN];          // split point per query
__device__ float2 g_qr  [SEG1 * NN];          // (rA, rB) = (f2/den, f1/den)

// ---------------- layer-1 GEMM: all 4 heads per block, X tile reused ----------------
__global__ __launch_bounds__(256)
void gemm1_kernel(const float* __restrict__ X,
                  const float* __restrict__ Wmat,
                  const float* __restrict__ avec) {
    __shared__ float XsT[64][68];   // [k][r]
    __shared__ float Ws [64][64];   // [k][d]
    const int tid = threadIdx.x;
    const int R0  = blockIdx.x * 64;
    const int rq  = tid >> 4;
    const int cq  = tid & 15;

    // stage X tile once (K = 64, single panel)
#pragma unroll
    for (int i = 0; i < 16; i++) {
        int idx = tid + i * 256;
        int r = idx >> 6, k = idx & 63;
        XsT[k][r] = X[(size_t)(R0 + r) * 64 + k];
    }

    for (int head = 0; head < HH; head++) {
        __syncthreads();
#pragma unroll
        for (int i = 0; i < 16; i++) {
            int idx = tid + i * 256;
            int k = idx >> 6, d = idx & 63;
            Ws[k][d] = Wmat[((size_t)head * 64 + k) * 64 + d];
        }
        __syncthreads();

        float acc[4][4];
#pragma unroll
        for (int i = 0; i < 4; i++)
#pragma unroll
            for (int j = 0; j < 4; j++) acc[i][j] = 0.f;

#pragma unroll 16
        for (int k = 0; k < 64; k++) {
            float4 xv = *(const float4*)&XsT[k][rq * 4];
            float4 wv = *(const float4*)&Ws [k][cq * 4];
            acc[0][0] += xv.x*wv.x; acc[0][1] += xv.x*wv.y; acc[0][2] += xv.x*wv.z; acc[0][3] += xv.x*wv.w;
            acc[1][0] += xv.y*wv.x; acc[1][1] += xv.y*wv.y; acc[1][2] += xv.y*wv.z; acc[1][3] += xv.y*wv.w;
            acc[2][0] += xv.z*wv.x; acc[2][1] += xv.z*wv.y; acc[2][2] += xv.z*wv.z; acc[2][3] += xv.z*wv.w;
            acc[3][0] += xv.w*wv.x; acc[3][1] += xv.w*wv.y; acc[3][2] += xv.w*wv.z; acc[3][3] += xv.w*wv.w;
        }

        float a1v[4], a2v[4];
#pragma unroll
        for (int j = 0; j < 4; j++) {
            a1v[j] = __ldg(&avec[head * 128 + cq * 4 + j]);
            a2v[j] = __ldg(&avec[head * 128 + 64 + cq * 4 + j]);
        }
#pragma unroll
        for (int i = 0; i < 4; i++) {
            int R = R0 + rq * 4 + i;
            int g = R >> 11;
            int n = R & (NN - 1);
            int seg = g * HH + head;
            size_t base = ((size_t)seg * NN + n) * 64 + cq * 4;
            float4 v; v.x = acc[i][0]; v.y = acc[i][1]; v.z = acc[i][2]; v.w = acc[i][3];
            *(float4*)&g_Hbuf[base] = v;

            float p1 = acc[i][0]*a1v[0] + acc[i][1]*a1v[1] + acc[i][2]*a1v[2] + acc[i][3]*a1v[3];
            float p2 = acc[i][0]*a2v[0] + acc[i][1]*a2v[1] + acc[i][2]*a2v[2] + acc[i][3]*a2v[3];
#pragma unroll
            for (int off = 8; off; off >>= 1) {
                p1 += __shfl_down_sync(0xffffffffu, p1, off, 16);
                p2 += __shfl_down_sync(0xffffffffu, p2, off, 16);
            }
            if (cq == 0) {
                g_s1[seg * NN + n] = p1;
                g_s2[seg * NN + n] = p2;
            }
        }
    }
}

// ---------------- layer-2 GEMM (K = 256) ----------------
__global__ __launch_bounds__(256)
void gemm2_kernel(const float* __restrict__ Wmat,
                  const float* __restrict__ avec) {
    __shared__ float XsT[64][68];
    __shared__ float Ws [64][64];
    const int tid = threadIdx.x;
    const int R0  = blockIdx.x * 64;
    const int rq  = tid >> 4;
    const int cq  = tid & 15;

    float acc[4][4];
#pragma unroll
    for (int i = 0; i < 4; i++)
#pragma unroll
        for (int j = 0; j < 4; j++) acc[i][j] = 0.f;

    for (int kp = 0; kp < 256; kp += 64) {
        __syncthreads();
#pragma unroll
        for (int i = 0; i < 16; i++) {
            int idx = tid + i * 256;
            int r = idx >> 6, k = idx & 63;
            XsT[k][r] = g_XC[(size_t)(R0 + r) * 256 + kp + k];
        }
#pragma unroll
        for (int i = 0; i < 16; i++) {
            int idx = tid + i * 256;
            int k = idx >> 6, d = idx & 63;
            Ws[k][d] = Wmat[((size_t)kp + k) * 64 + d];
        }
        __syncthreads();
#pragma unroll 16
        for (int k = 0; k < 64; k++) {
            float4 xv = *(const float4*)&XsT[k][rq * 4];
            float4 wv = *(const float4*)&Ws [k][cq * 4];
            acc[0][0] += xv.x*wv.x; acc[0][1] += xv.x*wv.y; acc[0][2] += xv.x*wv.z; acc[0][3] += xv.x*wv.w;
            acc[1][0] += xv.y*wv.x; acc[1][1] += xv.y*wv.y; acc[1][2] += xv.y*wv.z; acc[1][3] += xv.y*wv.w;
            acc[2][0] += xv.z*wv.x; acc[2][1] += xv.z*wv.y; acc[2][2] += xv.z*wv.z; acc[2][3] += xv.z*wv.w;
            acc[3][0] += xv.w*wv.x; acc[3][1] += xv.w*wv.y; acc[3][2] += xv.w*wv.z; acc[3][3] += xv.w*wv.w;
        }
    }

    float a1v[4], a2v[4];
#pragma unroll
    for (int j = 0; j < 4; j++) {
        a1v[j] = __ldg(&avec[cq * 4 + j]);
        a2v[j] = __ldg(&avec[64 + cq * 4 + j]);
    }
#pragma unroll
    for (int i = 0; i < 4; i++) {
        int R = R0 + rq * 4 + i;
        int seg = R >> 11;
        int n = R & (NN - 1);
        size_t base = ((size_t)seg * NN + n) * 64 + cq * 4;
        float4 v; v.x = acc[i][0]; v.y = acc[i][1]; v.z = acc[i][2]; v.w = acc[i][3];
        *(float4*)&g_H2[base] = v;

        float p1 = acc[i][0]*a1v[0] + acc[i][1]*a1v[1] + acc[i][2]*a1v[2] + acc[i][3]*a1v[3];
        float p2 = acc[i][0]*a2v[0] + acc[i][1]*a2v[1] + acc[i][2]*a2v[2] + acc[i][3]*a2v[3];
#pragma unroll
        for (int off = 8; off; off >>= 1) {
            p1 += __shfl_down_sync(0xffffffffu, p1, off, 16);
            p2 += __shfl_down_sync(0xffffffffu, p2, off, 16);
        }
        if (cq == 0) {
            g_s1[seg * NN + n] = p1;
            g_s2[seg * NN + n] = p2;
        }
    }
}

// ---------------- bitonic sort: 1024 threads, one comparator each ----------------
__global__ __launch_bounds__(1024)
void sort_kernel() {
    __shared__ float key[NN];
    __shared__ int   idx[NN];
    const int seg = blockIdx.x, tid = threadIdx.x;

    key[tid]        = g_s2[seg * NN + tid];        idx[tid]        = tid;
    key[tid + 1024] = g_s2[seg * NN + tid + 1024]; idx[tid + 1024] = tid + 1024;

    for (int k = 2; k <= NN; k <<= 1) {
        for (int j = k >> 1; j > 0; j >>= 1) {
            __syncthreads();
            int i = ((tid & ~(j - 1)) << 1) | (tid & (j - 1));
            int p = i | j;
            bool up = ((i & k) == 0);
            float ka = key[i], kb = key[p];
            if ((ka > kb) == up) {
                key[i] = kb; key[p] = ka;
                int t = idx[i]; idx[i] = idx[p]; idx[p] = t;
            }
        }
    }
    __syncthreads();

    float smaxv = key[NN - 1];
#pragma unroll
    for (int u = 0; u < 2; u++) {
        int i = tid + u * 1024;
        float kk = key[i];
        g_sorted[seg * NN + i] = kk;
        g_perm  [seg * NN + i] = idx[i];
        g_wsuf  [seg * NN + i] = expf(kk - smaxv);
        g_wpre  [seg * NN + i] = expf(ALPHA_ * (kk - smaxv));
    }
    if (tid == 0) g_smax[seg] = smaxv;
}

// ---------------- pass 3a: per-chunk sums, BOTH halves per thread (one H load) ----------------
__global__ __launch_bounds__(64)
void pass3a_kernel(int layer) {
    const int seg = blockIdx.x, c = blockIdx.y, d = threadIdx.x;
    const float* __restrict__ Hmat = (layer == 1) ? g_Hbuf : g_H2;
    const int q0 = c * CL;

    __shared__ int   sp[CL];
    __shared__ float swA[CL], swB[CL];
    sp [d] = g_perm[seg * NN + q0 + d];
    swA[d] = g_wpre[seg * NN + q0 + d];
    swB[d] = g_wsuf[seg * NN + q0 + d];
    __syncthreads();

    const size_t segNN = (size_t)seg * NN;
    float accA = 0.f, accB = 0.f;
#pragma unroll 8
    for (int q = 0; q < CL; q++) {
        float h = __ldg(&Hmat[(segNN + sp[q]) * 64 + d]);
        accA += swA[q] * h;
        accB += swB[q] * h;
    }
    g_CT[(seg * CH + c) * 128 + d]      = accA;
    g_CT[(seg * CH + c) * 128 + 64 + d] = accB;
}

// ---------------- pass 3b: chunk-offset scan + scalar scans ----------------
__global__ __launch_bounds__(256)
void pass3b_kernel() {
    const int seg = blockIdx.x, tid = threadIdx.x;
    const int lane = tid & 31, wid = tid >> 5;
    __shared__ float wsumA[8], wsumB[8], woffA[8], woffB[8];

    if (tid < 128) {
        float v[CH];
#pragma unroll
        for (int c = 0; c < CH; c++) v[c] = g_CT[(seg * CH + c) * 128 + tid];
        if (tid < 64) {
            float run = 0.f;
#pragma unroll
            for (int c = 0; c < CH; c++) { float t = v[c]; g_CT[(seg * CH + c) * 128 + tid] = run; run += t; }
            g_Ah[((size_t)seg * (NN + 1) + NN) * 64 + tid] = run;
        } else {
            float run = 0.f;
#pragma unroll
            for (int c = CH - 1; c >= 0; c--) { float t = v[c]; g_CT[(seg * CH + c) * 128 + tid] = run; run += t; }
            g_Bh[((size_t)seg * (NN + 1) + NN) * 64 + (tid - 64)] = 0.f;
        }
    }

    const int qb = tid * 8;
    float wa[8], wb[8];
    {
        float4 t0 = *(const float4*)&g_wpre[seg * NN + qb];
        float4 t1 = *(const float4*)&g_wpre[seg * NN + qb + 4];
        wa[0]=t0.x; wa[1]=t0.y; wa[2]=t0.z; wa[3]=t0.w;
        wa[4]=t1.x; wa[5]=t1.y; wa[6]=t1.z; wa[7]=t1.w;
        float4 u0 = *(const float4*)&g_wsuf[seg * NN + qb];
        float4 u1 = *(const float4*)&g_wsuf[seg * NN + qb + 4];
        wb[0]=u0.x; wb[1]=u0.y; wb[2]=u0.z; wb[3]=u0.w;
        wb[4]=u1.x; wb[5]=u1.y; wb[6]=u1.z; wb[7]=u1.w;
    }
    float la[8], lb[8];
    float sa = 0.f;
#pragma unroll
    for (int i = 0; i < 8; i++) { la[i] = sa; sa += wa[i]; }
    float sb = 0.f;
#pragma unroll
    for (int i = 7; i >= 0; i--) { sb += wb[i]; lb[i] = sb; }

    float xa = sa;
#pragma unroll
    for (int off = 1; off < 32; off <<= 1) {
        float y = __shfl_up_sync(0xffffffffu, xa, off);
        if (lane >= off) xa += y;
    }
    float exA = xa - sa;
    float xb = sb;
#pragma unroll
    for (int off = 1; off < 32; off <<= 1) {
        float y = __shfl_down_sync(0xffffffffu, xb, off);
        if (lane < 32 - off) xb += y;
    }
    float exB = xb - sb;

    if (lane == 31) wsumA[wid] = xa;
    if (lane == 0)  wsumB[wid] = xb;
    __syncthreads();
    if (tid == 0) {
        float r = 0.f;
        for (int w = 0; w < 8; w++) { float t = wsumA[w]; woffA[w] = r; r += t; }
        g_A1[seg * (NN + 1) + NN] = r;
        r = 0.f;
        for (int w = 7; w >= 0; w--) { float t = wsumB[w]; woffB[w] = r; r += t; }
        g_B1[seg * (NN + 1) + NN] = 0.f;
    }
    __syncthreads();
    float oa = woffA[wid] + exA, ob = woffB[wid] + exB;
#pragma unroll
    for (int i = 0; i < 8; i++) {
        g_A1[seg * (NN + 1) + qb + i] = oa + la[i];
        g_B1[seg * (NN + 1) + qb + i] = ob + lb[i];
    }
}

// ---------------- pass 3c: smem-staged tile, both scan directions ----------------
__global__ __launch_bounds__(128)
void pass3c_kernel(int layer) {
    const int seg = blockIdx.x, c = blockIdx.y, tid = threadIdx.x;
    const float* __restrict__ Hmat = (layer == 1) ? g_Hbuf : g_H2;
    const int q0 = c * CL;

    __shared__ int   sp[CL];
    __shared__ float swA[CL], swB[CL];
    __shared__ float tile[CL * 64];     // tile[q*64 + d]

    if (tid < 64) {
        sp [tid] = g_perm[seg * NN + q0 + tid];
        swA[tid] = g_wpre[seg * NN + q0 + tid];
    } else {
        swB[tid - 64] = g_wsuf[seg * NN + q0 + tid - 64];
    }
    __syncthreads();

    const size_t segNN = (size_t)seg * NN;
#pragma unroll
    for (int i = 0; i < 32; i++) {
        int lin = tid + 128 * i;
        int q = lin >> 6, d = lin & 63;
        tile[lin] = __ldg(&Hmat[(segNN + sp[q]) * 64 + d]);
    }
    __syncthreads();

    const int d = tid & 63;
    const size_t rowbase = ((size_t)seg * (NN + 1) + q0) * 64 + d;
    float run = g_CT[(seg * CH + c) * 128 + tid];

    if (tid < 64) {  // forward exclusive prefix of wpre*h
#pragma unroll 8
        for (int t = 0; t < CL; t++) {
            g_Ah[rowbase + (size_t)t * 64] = run;
            run += swA[t] * tile[t * 64 + d];
        }
    } else {         // reverse inclusive suffix of wsuf*h
#pragma unroll 8
        for (int t = CL - 1; t >= 0; t--) {
            run += swB[t] * tile[t * 64 + d];
            g_Bh[rowbase + (size_t)t * 64] = run;
        }
    }
}

// ---------------- qprep: one binary search + factor precompute per query ----------------
__global__ __launch_bounds__(256)
void qprep_kernel() {
    const int seg = blockIdx.x, tid = threadIdx.x;
    const int n = blockIdx.y * 256 + tid;

    __shared__ float srt[NN];
#pragma unroll
    for (int i = 0; i < 8; i++) srt[tid + 256 * i] = g_sorted[seg * NN + tid + 256 * i];
    __syncthreads();

    float s1v  = g_s1[seg * NN + n];
    float smax = g_smax[seg];
    float u = s1v + smax;
    float m = (u >= 0.f) ? u : ALPHA_ * u;
    float f1 = expf(u - m);
    float f2 = expf(ALPHA_ * u - m);
    float tau = -s1v;
    int lo = 0, hi = NN;
    while (lo < hi) {
        int mid = (lo + hi) >> 1;
        if (srt[mid] < tau) lo = mid + 1; else hi = mid;
    }
    int p = lo;
    float A1v = __ldg(&g_A1[seg * (NN + 1) + p]);
    float B1v = __ldg(&g_B1[seg * (NN + 1) + p]);
    float den = f1 * B1v + f2 * A1v;
    g_qp[seg * NN + n] = p;
    g_qr[seg * NN + n] = make_float2(f2 / den, f1 / den);
}

// ---------------- layer-1 combine: pure stream, elu -> XC ----------------
__global__ __launch_bounds__(256)
void combine1_kernel() {
    const int seg = blockIdx.y, tid = threadIdx.x;
    const int n  = blockIdx.x * 16 + (tid >> 4);
    const int d4 = (tid & 15) * 4;

    int    p = g_qp[seg * NN + n];
    float2 r = g_qr[seg * NN + n];
    size_t rb = ((size_t)seg * (NN + 1) + p) * 64 + d4;
    float4 a = *(const float4*)&g_Ah[rb];
    float4 b = *(const float4*)&g_Bh[rb];
    float4 o;
    o.x = r.y * b.x + r.x * a.x;
    o.y = r.y * b.y + r.x * a.y;
    o.z = r.y * b.z + r.x * a.z;
    o.w = r.y * b.w + r.x * a.w;
    o.x = (o.x > 0.f) ? o.x : expm1f(o.x);
    o.y = (o.y > 0.f) ? o.y : expm1f(o.y);
    o.z = (o.z > 0.f) ? o.z : expm1f(o.z);
    o.w = (o.w > 0.f) ? o.w : expm1f(o.w);

    int g = seg >> 2, h = seg & 3;
    *(float4*)&g_XC[((size_t)g * NN + n) * (HH * DD) + h * DD + d4] = o;
}

// ---------------- layer-2 combine: stream, elu -> log_softmax -> out ----------------
__global__ __launch_bounds__(256)
void combine2_kernel(float* __restrict__ out) {
    const int seg = blockIdx.y, tid = threadIdx.x;
    const int n  = blockIdx.x * 16 + (tid >> 4);
    const int d4 = (tid & 15) * 4;

    int    p = g_qp[seg * NN + n];
    float2 r = g_qr[seg * NN + n];
    size_t rb = ((size_t)seg * (NN + 1) + p) * 64 + d4;
    float4 a = *(const float4*)&g_Ah[rb];
    float4 b = *(const float4*)&g_Bh[rb];
    float4 o;
    o.x = r.y * b.x + r.x * a.x;
    o.y = r.y * b.y + r.x * a.y;
    o.z = r.y * b.z + r.x * a.z;
    o.w = r.y * b.w + r.x * a.w;
    o.x = (o.x > 0.f) ? o.x : expm1f(o.x);
    o.y = (o.y > 0.f) ? o.y : expm1f(o.y);
    o.z = (o.z > 0.f) ? o.z : expm1f(o.z);
    o.w = (o.w > 0.f) ? o.w : expm1f(o.w);

    // log_softmax over 64 dims: 16 lanes per row, 4 elems per lane
    float lm = fmaxf(fmaxf(o.x, o.y), fmaxf(o.z, o.w));
#pragma unroll
    for (int off = 8; off; off >>= 1)
        lm = fmaxf(lm, __shfl_xor_sync(0xffffffffu, lm, off, 16));
    float ls = expf(o.x - lm) + expf(o.y - lm) + expf(o.z - lm) + expf(o.w - lm);
#pragma unroll
    for (int off = 8; off; off >>= 1)
        ls += __shfl_xor_sync(0xffffffffu, ls, off, 16);
    float sub = lm + logf(ls);

    float4 w;
    w.x = o.x - sub; w.y = o.y - sub; w.z = o.z - sub; w.w = o.w - sub;
    *(float4*)&out[((size_t)seg * NN + n) * DD + d4] = w;
}

// ---------------- launch ----------------
extern "C" void kernel_launch(void* const* d_in, const int* in_sizes, int n_in,
                              void* d_out, int out_size) {
    const float* h_states = (const float*)d_in[0];
    const float* W_heads  = (const float*)d_in[1];
    const float* a_heads  = (const float*)d_in[2];
    const float* W_out    = (const float*)d_in[3];
    const float* a_out    = (const float*)d_in[4];
    float* out = (float*)d_out;

    // ---- layer 1 ----
    gemm1_kernel<<<BB * NN / 64, 256>>>(h_states, W_heads, a_heads);
    sort_kernel<<<SEG1, 1024>>>();
    pass3a_kernel<<<dim3(SEG1, CH), 64>>>(1);
    pass3b_kernel<<<SEG1, 256>>>();
    pass3c_kernel<<<dim3(SEG1, CH), 128>>>(1);
    qprep_kernel<<<dim3(SEG1, NN / 256), 256>>>();
    combine1_kernel<<<dim3(NN / 16, SEG1), 256>>>();

    // ---- layer 2 ----
    gemm2_kernel<<<BB * NN / 64, 256>>>(W_out, a_out);
    sort_kernel<<<BB, 1024>>>();
    pass3a_kernel<<<dim3(BB, CH), 64>>>(2);
    pass3b_kernel<<<BB, 256>>>();
    pass3c_kernel<<<dim3(BB, CH), 128>>>(2);
    qprep_kernel<<<dim3(BB, NN / 256), 256>>>();
    combine2_kernel<<<dim3(NN / 16, BB), 256>>>(out);
}